// round 1
// baseline (speedup 1.0000x reference)
#include <cuda_runtime.h>
#include <cstdint>

#define G_SEG   4096
#define D       128
#define DV4     32            // float4 per row (128 floats)
#define CAP     200           // rows cached in smem per segment
#define NTHR    256
#define ROWG    8             // NTHR / 32 row-groups
#define EPS     1e-5f

__device__ int g_start[G_SEG + 1];

// ---------------------------------------------------------------------------
// Kernel 1: segment boundaries from sorted segment_ids.
// g_start[g] = first row index with segment_ids >= g ; g_start[G] = n.
// ---------------------------------------------------------------------------
__global__ void seg_bounds_kernel(const int* __restrict__ seg, int n) {
    int i = blockIdx.x * blockDim.x + threadIdx.x;
    if (i > n) return;
    if (i == 0) {
        int s0 = seg[0];
        for (int g = 0; g <= s0; ++g) g_start[g] = 0;
    } else if (i == n) {
        int sl = seg[n - 1];
        for (int g = sl + 1; g <= G_SEG; ++g) g_start[g] = n;
    } else {
        int a = seg[i - 1], b = seg[i];
        if (a != b) {
            for (int g = a + 1; g <= b; ++g) g_start[g] = i;
        }
    }
}

// ---------------------------------------------------------------------------
// Kernel 2: one CTA per segment. Single global read of features via smem cache.
//   pass 1: LDG.128 rows, cache first CAP rows in smem, accumulate sum/sumsq
//   reduce: 8 row-groups -> per-dim mean/var -> affine coeffs A,B per dim
//   pass 2: replay rows from smem (or L2 for overflow), write A*x+B
// ---------------------------------------------------------------------------
extern __shared__ float4 smem[];   // [CAP*32] cache | [256] redS | [256] redQ | [64] AB

__global__ __launch_bounds__(NTHR, 2)
void graphnorm_kernel(const float4* __restrict__ feat,
                      const float4* __restrict__ weight,
                      const float4* __restrict__ bias,
                      const float4* __restrict__ mscale,
                      float4* __restrict__ out) {
    const int g = blockIdx.x;
    const int s = g_start[g];
    const int e = g_start[g + 1];
    const int cnt = e - s;
    if (cnt <= 0) return;

    const int t    = threadIdx.x;
    const int lane = t & 31;      // which float4 of the row (dims lane*4..lane*4+3)
    const int rg   = t >> 5;      // row-group 0..7

    float4* cache = smem;                 // CAP*32 float4
    float4* redS  = smem + CAP * DV4;     // 256
    float4* redQ  = redS + NTHR;          // 256
    float4* AB    = redQ + NTHR;          // 64: A[0..31], B[32..63]

    const float4* base = feat + (size_t)s * DV4;

    float4 sm = make_float4(0.f, 0.f, 0.f, 0.f);
    float4 sq = make_float4(0.f, 0.f, 0.f, 0.f);

    const int ncache = cnt < CAP ? cnt : CAP;

    // ---- pass 1a: cached region (LDG -> STS + accumulate) ----
    #pragma unroll 4
    for (int r = rg; r < ncache; r += ROWG) {
        float4 v = base[r * DV4 + lane];
        cache[r * DV4 + lane] = v;
        sm.x += v.x; sm.y += v.y; sm.z += v.z; sm.w += v.w;
        sq.x += v.x * v.x; sq.y += v.y * v.y; sq.z += v.z * v.z; sq.w += v.w * v.w;
    }
    // ---- pass 1b: overflow rows (LDG only) ----
    #pragma unroll 4
    for (int r = CAP + rg; r < cnt; r += ROWG) {
        float4 v = base[r * DV4 + lane];
        sm.x += v.x; sm.y += v.y; sm.z += v.z; sm.w += v.w;
        sq.x += v.x * v.x; sq.y += v.y * v.y; sq.z += v.z * v.z; sq.w += v.w * v.w;
    }

    redS[t] = sm;
    redQ[t] = sq;
    __syncthreads();

    // ---- per-dim stats + affine coefficients (first warp only) ----
    if (t < 32) {
        float4 S = redS[t], Q = redQ[t];
        #pragma unroll
        for (int j = 1; j < ROWG; ++j) {
            float4 a = redS[j * 32 + t], b = redQ[j * 32 + t];
            S.x += a.x; S.y += a.y; S.z += a.z; S.w += a.w;
            Q.x += b.x; Q.y += b.y; Q.z += b.z; Q.w += b.w;
        }
        const float ic = 1.0f / (float)cnt;
        float4 w  = weight[t];
        float4 b4 = bias[t];
        float4 sc = mscale[t];
        float4 A, B;
        {
            float m = S.x * ic, q = Q.x * ic;
            float var = q - m * m * sc.x * (2.0f - sc.x);
            A.x = w.x * rsqrtf(var + EPS);
            B.x = b4.x - m * sc.x * A.x;
        }
        {
            float m = S.y * ic, q = Q.y * ic;
            float var = q - m * m * sc.y * (2.0f - sc.y);
            A.y = w.y * rsqrtf(var + EPS);
            B.y = b4.y - m * sc.y * A.y;
        }
        {
            float m = S.z * ic, q = Q.z * ic;
            float var = q - m * m * sc.z * (2.0f - sc.z);
            A.z = w.z * rsqrtf(var + EPS);
            B.z = b4.z - m * sc.z * A.z;
        }
        {
            float m = S.w * ic, q = Q.w * ic;
            float var = q - m * m * sc.w * (2.0f - sc.w);
            A.w = w.w * rsqrtf(var + EPS);
            B.w = b4.w - m * sc.w * A.w;
        }
        AB[t]      = A;
        AB[32 + t] = B;
    }
    __syncthreads();

    const float4 A = AB[lane];
    const float4 B = AB[32 + lane];
    float4* obase = out + (size_t)s * DV4;

    // ---- pass 2a: cached rows (LDS -> STG) ----
    #pragma unroll 4
    for (int r = rg; r < ncache; r += ROWG) {
        float4 v = cache[r * DV4 + lane];
        float4 o;
        o.x = fmaf(v.x, A.x, B.x);
        o.y = fmaf(v.y, A.y, B.y);
        o.z = fmaf(v.z, A.z, B.z);
        o.w = fmaf(v.w, A.w, B.w);
        obase[r * DV4 + lane] = o;
    }
    // ---- pass 2b: overflow rows (LDG from L2 -> STG) ----
    #pragma unroll 4
    for (int r = CAP + rg; r < cnt; r += ROWG) {
        float4 v = base[r * DV4 + lane];
        float4 o;
        o.x = fmaf(v.x, A.x, B.x);
        o.y = fmaf(v.y, A.y, B.y);
        o.z = fmaf(v.z, A.z, B.z);
        o.w = fmaf(v.w, A.w, B.w);
        obase[r * DV4 + lane] = o;
    }
}

// ---------------------------------------------------------------------------
// Launch
// inputs: [0] features (N*D f32), [1] segment_ids (N i32), [2] num_graphs,
//         [3] weight (D), [4] bias (D), [5] mean_scale (D)
// output: N*D f32
// ---------------------------------------------------------------------------
extern "C" void kernel_launch(void* const* d_in, const int* in_sizes, int n_in,
                              void* d_out, int out_size) {
    const float* feat = (const float*)d_in[0];
    const int*   seg  = (const int*)d_in[1];
    const float* w    = (const float*)d_in[3];
    const float* b    = (const float*)d_in[4];
    const float* ms   = (const float*)d_in[5];
    const int n = in_sizes[1];   // number of rows

    // boundaries
    {
        int threads = 256;
        int blocks  = (n + 1 + threads - 1) / threads;
        seg_bounds_kernel<<<blocks, threads>>>(seg, n);
    }

    // normalization
    {
        const size_t smem_bytes = (size_t)(CAP * DV4 + NTHR + NTHR + 64) * sizeof(float4);
        static bool attr_set = false;
        if (!attr_set) {
            cudaFuncSetAttribute(graphnorm_kernel,
                                 cudaFuncAttributeMaxDynamicSharedMemorySize,
                                 (int)smem_bytes);
            attr_set = true;
        }
        graphnorm_kernel<<<G_SEG, NTHR, smem_bytes>>>(
            (const float4*)feat, (const float4*)w, (const float4*)b,
            (const float4*)ms, (float4*)d_out);
    }
}

// round 5
// speedup vs baseline: 1.0583x; 1.0583x over previous
#include <cuda_runtime.h>
#include <cstdint>

#define G_SEG   4096
#define D       128
#define DV4     32            // float4 per row (128 floats)
#define NTHR    256
#define ROWG    8             // NTHR / 32 row-groups
#define EPS     1e-5f

__device__ int g_start[G_SEG + 1];

// ---------------------------------------------------------------------------
// Kernel 1: segment boundaries from sorted segment_ids.
// ---------------------------------------------------------------------------
__global__ void seg_bounds_kernel(const int* __restrict__ seg, int n) {
    int i = blockIdx.x * blockDim.x + threadIdx.x;
    if (i > n) return;
    if (i == 0) {
        int s0 = seg[0];
        for (int g = 0; g <= s0; ++g) g_start[g] = 0;
    } else if (i == n) {
        int sl = seg[n - 1];
        for (int g = sl + 1; g <= G_SEG; ++g) g_start[g] = n;
    } else {
        int a = seg[i - 1], b = seg[i];
        if (a != b) {
            for (int g = a + 1; g <= b; ++g) g_start[g] = i;
        }
    }
}

// ---------------------------------------------------------------------------
// Kernel 2: one CTA per segment, NO smem row cache.
// pass 1: stream segment rows (LDG.128, default caching -> lands in L2),
//         accumulate per-dim sum / sumsq in registers.
// reduce: 8 row-groups -> per-dim affine coeffs A,B.
// pass 2: re-read rows (L2 hit, __ldcs streaming) -> fmaf -> __stcs store.
// Concurrent working set (~5 CTAs/SM * 125KB * 148SM ~ 90MB) fits in 126MB L2.
// ---------------------------------------------------------------------------
__global__ __launch_bounds__(NTHR, 4)
void graphnorm_kernel(const float4* __restrict__ feat,
                      const float4* __restrict__ weight,
                      const float4* __restrict__ bias,
                      const float4* __restrict__ mscale,
                      float4* __restrict__ out) {
    __shared__ float4 redS[NTHR];
    __shared__ float4 redQ[NTHR];
    __shared__ float4 AB[64];            // A[0..31], B[32..63]

    const int g = blockIdx.x;
    const int s = g_start[g];
    const int e = g_start[g + 1];
    const int cnt = e - s;
    if (cnt <= 0) return;

    const int t    = threadIdx.x;
    const int lane = t & 31;      // which float4 of the row
    const int rg   = t >> 5;      // row-group 0..7

    const float4* base = feat + (size_t)s * DV4;

    float4 sm = make_float4(0.f, 0.f, 0.f, 0.f);
    float4 sq = make_float4(0.f, 0.f, 0.f, 0.f);

    // ---- pass 1: accumulate ----
    #pragma unroll 4
    for (int r = rg; r < cnt; r += ROWG) {
        float4 v = base[r * DV4 + lane];
        sm.x += v.x; sm.y += v.y; sm.z += v.z; sm.w += v.w;
        sq.x = fmaf(v.x, v.x, sq.x);
        sq.y = fmaf(v.y, v.y, sq.y);
        sq.z = fmaf(v.z, v.z, sq.z);
        sq.w = fmaf(v.w, v.w, sq.w);
    }

    redS[t] = sm;
    redQ[t] = sq;
    __syncthreads();

    // ---- per-dim stats + affine coefficients (first warp) ----
    if (t < 32) {
        float4 S = redS[t], Q = redQ[t];
        #pragma unroll
        for (int j = 1; j < ROWG; ++j) {
            float4 a = redS[j * 32 + t], b = redQ[j * 32 + t];
            S.x += a.x; S.y += a.y; S.z += a.z; S.w += a.w;
            Q.x += b.x; Q.y += b.y; Q.z += b.z; Q.w += b.w;
        }
        const float ic = 1.0f / (float)cnt;
        float4 w  = weight[t];
        float4 b4 = bias[t];
        float4 sc = mscale[t];
        float4 A, B;
        {
            float m = S.x * ic, q = Q.x * ic;
            float var = q - m * m * sc.x * (2.0f - sc.x);
            A.x = w.x * rsqrtf(var + EPS);
            B.x = b4.x - m * sc.x * A.x;
        }
        {
            float m = S.y * ic, q = Q.y * ic;
            float var = q - m * m * sc.y * (2.0f - sc.y);
            A.y = w.y * rsqrtf(var + EPS);
            B.y = b4.y - m * sc.y * A.y;
        }
        {
            float m = S.z * ic, q = Q.z * ic;
            float var = q - m * m * sc.z * (2.0f - sc.z);
            A.z = w.z * rsqrtf(var + EPS);
            B.z = b4.z - m * sc.z * A.z;
        }
        {
            float m = S.w * ic, q = Q.w * ic;
            float var = q - m * m * sc.w * (2.0f - sc.w);
            A.w = w.w * rsqrtf(var + EPS);
            B.w = b4.w - m * sc.w * A.w;
        }
        AB[t]      = A;
        AB[32 + t] = B;
    }
    __syncthreads();

    const float4 A = AB[lane];
    const float4 B = AB[32 + lane];
    float4* obase = out + (size_t)s * DV4;

    // ---- pass 2: re-read (L2 hit, streaming) -> affine -> streaming store ----
    #pragma unroll 4
    for (int r = rg; r < cnt; r += ROWG) {
        float4 v = __ldcs(&base[r * DV4 + lane]);
        float4 o;
        o.x = fmaf(v.x, A.x, B.x);
        o.y = fmaf(v.y, A.y, B.y);
        o.z = fmaf(v.z, A.z, B.z);
        o.w = fmaf(v.w, A.w, B.w);
        __stcs(&obase[r * DV4 + lane], o);
    }
}

// ---------------------------------------------------------------------------
// Launch
// inputs: [0] features (N*D f32), [1] segment_ids (N i32), [2] num_graphs,
//         [3] weight (D), [4] bias (D), [5] mean_scale (D)
// ---------------------------------------------------------------------------
extern "C" void kernel_launch(void* const* d_in, const int* in_sizes, int n_in,
                              void* d_out, int out_size) {
    const float* feat = (const float*)d_in[0];
    const int*   seg  = (const int*)d_in[1];
    const float* w    = (const float*)d_in[3];
    const float* b    = (const float*)d_in[4];
    const float* ms   = (const float*)d_in[5];
    const int n = in_sizes[1];   // number of rows

    {
        int threads = 256;
        int blocks  = (n + 1 + threads - 1) / threads;
        seg_bounds_kernel<<<blocks, threads>>>(seg, n);
    }

    graphnorm_kernel<<<G_SEG, NTHR>>>(
        (const float4*)feat, (const float4*)w, (const float4*)b,
        (const float4*)ms, (float4*)d_out);
}

// round 6
// speedup vs baseline: 1.2315x; 1.1637x over previous
#include <cuda_runtime.h>
#include <cstdint>

#define G_SEG   4096
#define D       128
#define DV4     32            // float4 per row (128 floats)
#define NTHR    256
#define ROWG    8             // NTHR / 32 row-groups
#define UNR     8             // rows per warp per outer iteration
#define EPS     1e-5f

__device__ int g_start[G_SEG + 1];

// ---------------------------------------------------------------------------
// Kernel 1: segment boundaries from sorted segment_ids.
// ---------------------------------------------------------------------------
__global__ void seg_bounds_kernel(const int* __restrict__ seg, int n) {
    int i = blockIdx.x * blockDim.x + threadIdx.x;
    if (i > n) return;
    if (i == 0) {
        int s0 = seg[0];
        for (int g = 0; g <= s0; ++g) g_start[g] = 0;
    } else if (i == n) {
        int sl = seg[n - 1];
        for (int g = sl + 1; g <= G_SEG; ++g) g_start[g] = n;
    } else {
        int a = seg[i - 1], b = seg[i];
        if (a != b) {
            for (int g = a + 1; g <= b; ++g) g_start[g] = i;
        }
    }
}

// ---------------------------------------------------------------------------
// Kernel 2: one CTA per segment.
// pass 1: stream rows, 8 independent LDG.128 in flight per warp, accumulate
//         per-dim sum/sumsq in regs.
// single barrier; then EVERY thread reduces the 8 row-group partials for its
// lane and derives affine coeffs A,B in registers (no 2nd barrier).
// pass 2: re-read rows (L2 hit, __ldcs) -> fmaf -> __stcs, unroll 8.
// ---------------------------------------------------------------------------
__global__ __launch_bounds__(NTHR, 3)
void graphnorm_kernel(const float4* __restrict__ feat,
                      const float4* __restrict__ weight,
                      const float4* __restrict__ bias,
                      const float4* __restrict__ mscale,
                      float4* __restrict__ out) {
    __shared__ float4 redS[NTHR];
    __shared__ float4 redQ[NTHR];

    const int g = blockIdx.x;
    const int s = g_start[g];
    const int e = g_start[g + 1];
    const int cnt = e - s;
    if (cnt <= 0) return;

    const int t    = threadIdx.x;
    const int lane = t & 31;      // which float4 of the row
    const int rg   = t >> 5;      // row-group 0..7

    const float4* base = feat + (size_t)s * DV4;

    float4 sm = make_float4(0.f, 0.f, 0.f, 0.f);
    float4 sq = make_float4(0.f, 0.f, 0.f, 0.f);

    // ---- pass 1: accumulate, 8 rows per warp-iteration ----
    int r = rg;
    const int full_end = cnt - (UNR - 1) * ROWG;   // loop while r + 7*ROWG < cnt
    for (; r < full_end; r += UNR * ROWG) {
        float4 v0 = base[(r + 0 * ROWG) * DV4 + lane];
        float4 v1 = base[(r + 1 * ROWG) * DV4 + lane];
        float4 v2 = base[(r + 2 * ROWG) * DV4 + lane];
        float4 v3 = base[(r + 3 * ROWG) * DV4 + lane];
        float4 v4 = base[(r + 4 * ROWG) * DV4 + lane];
        float4 v5 = base[(r + 5 * ROWG) * DV4 + lane];
        float4 v6 = base[(r + 6 * ROWG) * DV4 + lane];
        float4 v7 = base[(r + 7 * ROWG) * DV4 + lane];

        sm.x += v0.x + v1.x + v2.x + v3.x + v4.x + v5.x + v6.x + v7.x;
        sm.y += v0.y + v1.y + v2.y + v3.y + v4.y + v5.y + v6.y + v7.y;
        sm.z += v0.z + v1.z + v2.z + v3.z + v4.z + v5.z + v6.z + v7.z;
        sm.w += v0.w + v1.w + v2.w + v3.w + v4.w + v5.w + v6.w + v7.w;

        sq.x = fmaf(v0.x, v0.x, sq.x); sq.x = fmaf(v1.x, v1.x, sq.x);
        sq.x = fmaf(v2.x, v2.x, sq.x); sq.x = fmaf(v3.x, v3.x, sq.x);
        sq.x = fmaf(v4.x, v4.x, sq.x); sq.x = fmaf(v5.x, v5.x, sq.x);
        sq.x = fmaf(v6.x, v6.x, sq.x); sq.x = fmaf(v7.x, v7.x, sq.x);

        sq.y = fmaf(v0.y, v0.y, sq.y); sq.y = fmaf(v1.y, v1.y, sq.y);
        sq.y = fmaf(v2.y, v2.y, sq.y); sq.y = fmaf(v3.y, v3.y, sq.y);
        sq.y = fmaf(v4.y, v4.y, sq.y); sq.y = fmaf(v5.y, v5.y, sq.y);
        sq.y = fmaf(v6.y, v6.y, sq.y); sq.y = fmaf(v7.y, v7.y, sq.y);

        sq.z = fmaf(v0.z, v0.z, sq.z); sq.z = fmaf(v1.z, v1.z, sq.z);
        sq.z = fmaf(v2.z, v2.z, sq.z); sq.z = fmaf(v3.z, v3.z, sq.z);
        sq.z = fmaf(v4.z, v4.z, sq.z); sq.z = fmaf(v5.z, v5.z, sq.z);
        sq.z = fmaf(v6.z, v6.z, sq.z); sq.z = fmaf(v7.z, v7.z, sq.z);

        sq.w = fmaf(v0.w, v0.w, sq.w); sq.w = fmaf(v1.w, v1.w, sq.w);
        sq.w = fmaf(v2.w, v2.w, sq.w); sq.w = fmaf(v3.w, v3.w, sq.w);
        sq.w = fmaf(v4.w, v4.w, sq.w); sq.w = fmaf(v5.w, v5.w, sq.w);
        sq.w = fmaf(v6.w, v6.w, sq.w); sq.w = fmaf(v7.w, v7.w, sq.w);
    }
    // remainder
    for (; r < cnt; r += ROWG) {
        float4 v = base[r * DV4 + lane];
        sm.x += v.x; sm.y += v.y; sm.z += v.z; sm.w += v.w;
        sq.x = fmaf(v.x, v.x, sq.x);
        sq.y = fmaf(v.y, v.y, sq.y);
        sq.z = fmaf(v.z, v.z, sq.z);
        sq.w = fmaf(v.w, v.w, sq.w);
    }

    redS[t] = sm;
    redQ[t] = sq;
    __syncthreads();

    // ---- every thread reduces its lane's 8 partials + computes A,B ----
    float4 S = redS[lane], Q = redQ[lane];
    #pragma unroll
    for (int j = 1; j < ROWG; ++j) {
        float4 a = redS[j * 32 + lane], b = redQ[j * 32 + lane];
        S.x += a.x; S.y += a.y; S.z += a.z; S.w += a.w;
        Q.x += b.x; Q.y += b.y; Q.z += b.z; Q.w += b.w;
    }

    const float ic = 1.0f / (float)cnt;
    const float4 w  = weight[lane];
    const float4 b4 = bias[lane];
    const float4 sc = mscale[lane];
    float4 A, B;
    {
        float m = S.x * ic, q = Q.x * ic;
        float var = q - m * m * sc.x * (2.0f - sc.x);
        A.x = w.x * rsqrtf(var + EPS);
        B.x = b4.x - m * sc.x * A.x;
    }
    {
        float m = S.y * ic, q = Q.y * ic;
        float var = q - m * m * sc.y * (2.0f - sc.y);
        A.y = w.y * rsqrtf(var + EPS);
        B.y = b4.y - m * sc.y * A.y;
    }
    {
        float m = S.z * ic, q = Q.z * ic;
        float var = q - m * m * sc.z * (2.0f - sc.z);
        A.z = w.z * rsqrtf(var + EPS);
        B.z = b4.z - m * sc.z * A.z;
    }
    {
        float m = S.w * ic, q = Q.w * ic;
        float var = q - m * m * sc.w * (2.0f - sc.w);
        A.w = w.w * rsqrtf(var + EPS);
        B.w = b4.w - m * sc.w * A.w;
    }

    float4* obase = out + (size_t)s * DV4;

    // ---- pass 2: L2 re-read -> affine -> streaming store, unroll 8 ----
    r = rg;
    for (; r < full_end; r += UNR * ROWG) {
        float4 v0 = __ldcs(&base[(r + 0 * ROWG) * DV4 + lane]);
        float4 v1 = __ldcs(&base[(r + 1 * ROWG) * DV4 + lane]);
        float4 v2 = __ldcs(&base[(r + 2 * ROWG) * DV4 + lane]);
        float4 v3 = __ldcs(&base[(r + 3 * ROWG) * DV4 + lane]);
        float4 v4 = __ldcs(&base[(r + 4 * ROWG) * DV4 + lane]);
        float4 v5 = __ldcs(&base[(r + 5 * ROWG) * DV4 + lane]);
        float4 v6 = __ldcs(&base[(r + 6 * ROWG) * DV4 + lane]);
        float4 v7 = __ldcs(&base[(r + 7 * ROWG) * DV4 + lane]);

        float4 o;
        o.x = fmaf(v0.x, A.x, B.x); o.y = fmaf(v0.y, A.y, B.y);
        o.z = fmaf(v0.z, A.z, B.z); o.w = fmaf(v0.w, A.w, B.w);
        __stcs(&obase[(r + 0 * ROWG) * DV4 + lane], o);
        o.x = fmaf(v1.x, A.x, B.x); o.y = fmaf(v1.y, A.y, B.y);
        o.z = fmaf(v1.z, A.z, B.z); o.w = fmaf(v1.w, A.w, B.w);
        __stcs(&obase[(r + 1 * ROWG) * DV4 + lane], o);
        o.x = fmaf(v2.x, A.x, B.x); o.y = fmaf(v2.y, A.y, B.y);
        o.z = fmaf(v2.z, A.z, B.z); o.w = fmaf(v2.w, A.w, B.w);
        __stcs(&obase[(r + 2 * ROWG) * DV4 + lane], o);
        o.x = fmaf(v3.x, A.x, B.x); o.y = fmaf(v3.y, A.y, B.y);
        o.z = fmaf(v3.z, A.z, B.z); o.w = fmaf(v3.w, A.w, B.w);
        __stcs(&obase[(r + 3 * ROWG) * DV4 + lane], o);
        o.x = fmaf(v4.x, A.x, B.x); o.y = fmaf(v4.y, A.y, B.y);
        o.z = fmaf(v4.z, A.z, B.z); o.w = fmaf(v4.w, A.w, B.w);
        __stcs(&obase[(r + 4 * ROWG) * DV4 + lane], o);
        o.x = fmaf(v5.x, A.x, B.x); o.y = fmaf(v5.y, A.y, B.y);
        o.z = fmaf(v5.z, A.z, B.z); o.w = fmaf(v5.w, A.w, B.w);
        __stcs(&obase[(r + 5 * ROWG) * DV4 + lane], o);
        o.x = fmaf(v6.x, A.x, B.x); o.y = fmaf(v6.y, A.y, B.y);
        o.z = fmaf(v6.z, A.z, B.z); o.w = fmaf(v6.w, A.w, B.w);
        __stcs(&obase[(r + 6 * ROWG) * DV4 + lane], o);
        o.x = fmaf(v7.x, A.x, B.x); o.y = fmaf(v7.y, A.y, B.y);
        o.z = fmaf(v7.z, A.z, B.z); o.w = fmaf(v7.w, A.w, B.w);
        __stcs(&obase[(r + 7 * ROWG) * DV4 + lane], o);
    }
    for (; r < cnt; r += ROWG) {
        float4 v = __ldcs(&base[r * DV4 + lane]);
        float4 o;
        o.x = fmaf(v.x, A.x, B.x);
        o.y = fmaf(v.y, A.y, B.y);
        o.z = fmaf(v.z, A.z, B.z);
        o.w = fmaf(v.w, A.w, B.w);
        __stcs(&obase[r * DV4 + lane], o);
    }
}

// ---------------------------------------------------------------------------
// Launch
// inputs: [0] features (N*D f32), [1] segment_ids (N i32), [2] num_graphs,
//         [3] weight (D), [4] bias (D), [5] mean_scale (D)
// ---------------------------------------------------------------------------
extern "C" void kernel_launch(void* const* d_in, const int* in_sizes, int n_in,
                              void* d_out, int out_size) {
    const float* feat = (const float*)d_in[0];
    const int*   seg  = (const int*)d_in[1];
    const float* w    = (const float*)d_in[3];
    const float* b    = (const float*)d_in[4];
    const float* ms   = (const float*)d_in[5];
    const int n = in_sizes[1];   // number of rows

    {
        int threads = 256;
        int blocks  = (n + 1 + threads - 1) / threads;
        seg_bounds_kernel<<<blocks, threads>>>(seg, n);
    }

    graphnorm_kernel<<<G_SEG, NTHR>>>(
        (const float4*)feat, (const float4*)w, (const float4*)b,
        (const float4*)ms, (float4*)d_out);
}